// round 16
// baseline (speedup 1.0000x reference)
#include <cuda_runtime.h>
#include <cuda_bf16.h>
#include <math.h>
#include <stdint.h>

// Problem constants
constexpr int B  = 2;
constexpr int S  = 1024;
constexpr int V  = 32000;
constexpr int D  = 1024;
constexpr int DH = 4096;
constexpr int NL = 4;
constexpr int NH = 16;
constexpr int HD = 64;
constexpr int M  = B * S;

// ---------------------------------------------------------------------------
// Scratch (device globals)
// ---------------------------------------------------------------------------
__device__ float g_h[M * D];
__device__ float g_a[M * D];
__device__ float g_q[M * D];
__device__ float g_k[M * D];
__device__ float g_v[M * D];
__device__ float g_t[M * D];
__device__ float g_f[M * DH];

// ---------------------------------------------------------------------------
// Embedding + positional encoding (R15-exact)
// ---------------------------------------------------------------------------
__global__ void embed_kernel(const int* __restrict__ x,
                             const float* __restrict__ emb,
                             const float* __restrict__ pe,
                             float* __restrict__ out)
{
    const int i   = blockIdx.x;
    const int s   = i % S;
    const int tok = x[i];
    const float4* e = reinterpret_cast<const float4*>(emb + (size_t)tok * D);
    const float4* p = reinterpret_cast<const float4*>(pe  + (size_t)s   * D);
    float4*       o = reinterpret_cast<float4*>(out + (size_t)i * D);
    const int t = threadIdx.x;
    float4 a = e[t], b = p[t];
    o[t] = make_float4(a.x + b.x, a.y + b.y, a.z + b.z, a.w + b.w);
}

// ---------------------------------------------------------------------------
// LayerNorm (R15-exact)
// ---------------------------------------------------------------------------
__global__ void ln_kernel(const float* __restrict__ X,
                          const float* __restrict__ gam,
                          const float* __restrict__ bet,
                          float* __restrict__ Y)
{
    const int row = blockIdx.x;
    const float* x = X + (size_t)row * D;
    float*       y = Y + (size_t)row * D;
    __shared__ float sred[8];
    const int tid = threadIdx.x;

    float s = 0.f;
    for (int d = tid; d < D; d += 256) s += x[d];
    #pragma unroll
    for (int o = 16; o > 0; o >>= 1) s += __shfl_xor_sync(0xffffffffu, s, o);
    if ((tid & 31) == 0) sred[tid >> 5] = s;
    __syncthreads();
    float mean = 0.f;
    #pragma unroll
    for (int w = 0; w < 8; w++) mean += sred[w];
    mean *= (1.0f / D);
    __syncthreads();

    float vs = 0.f;
    for (int d = tid; d < D; d += 256) { float t = x[d] - mean; vs += t * t; }
    #pragma unroll
    for (int o = 16; o > 0; o >>= 1) vs += __shfl_xor_sync(0xffffffffu, vs, o);
    if ((tid & 31) == 0) sred[tid >> 5] = vs;
    __syncthreads();
    float var = 0.f;
    #pragma unroll
    for (int w = 0; w < 8; w++) var += sred[w];
    var *= (1.0f / D);
    const float rstd = rsqrtf(var + 1e-5f);

    for (int d = tid; d < D; d += 256)
        y[d] = (x[d] - mean) * rstd * gam[d] + bet[d];
}

// ---------------------------------------------------------------------------
// tf32 helpers
// ---------------------------------------------------------------------------
__device__ __forceinline__ uint32_t f2tf(float x) {
    uint32_t r;
    asm("cvt.rna.tf32.f32 %0, %1;" : "=r"(r) : "f"(x));
    return r;
}

__device__ __forceinline__ void mma_tf32(float* d,
                                         const uint32_t* a,
                                         const uint32_t* b)
{
    asm volatile(
        "mma.sync.aligned.m16n8k8.row.col.f32.tf32.tf32.f32 "
        "{%0,%1,%2,%3}, {%4,%5,%6,%7}, {%8,%9}, {%0,%1,%2,%3};\n"
        : "+f"(d[0]), "+f"(d[1]), "+f"(d[2]), "+f"(d[3])
        : "r"(a[0]), "r"(a[1]), "r"(a[2]), "r"(a[3]),
          "r"(b[0]), "r"(b[1]));
}

__device__ __forceinline__ void cp16(uint32_t dst_smem, const void* src) {
    asm volatile("cp.async.ca.shared.global [%0], [%1], 16;"
                 :: "r"(dst_smem), "l"(src));
}
__device__ __forceinline__ void cp_commit() {
    asm volatile("cp.async.commit_group;");
}
template<int N>
__device__ __forceinline__ void cp_wait() {
    asm volatile("cp.async.wait_group %0;" :: "n"(N));
}

// ---------------------------------------------------------------------------
// TF32 tensor-core GEMM, cp.async 4-stage pipeline (R15-exact, BM=128 only)
// ---------------------------------------------------------------------------
constexpr int AS = 20;                    // A row stride (words), [row][k]
constexpr int BS = 136;                   // B row stride (words), [k][col]
constexpr int ASZ = 128 * AS;             // 2560 words / stage
constexpr int BSZ = 16 * BS;              // 2176 words / stage
constexpr int NSTG = 4;
constexpr int GEMM_SMEM = NSTG * (ASZ + BSZ) * 4;   // 75776 B

template<bool HAS_BIAS, bool HAS_RES, bool RELU>
__device__ __forceinline__
void gemm_body(int N, int K,
               const float* __restrict__ A,
               const float* __restrict__ Bm,
               const float* __restrict__ bias,
               const float* __restrict__ res,
               float* __restrict__ C,
               int bx, int by)
{
    extern __shared__ float smem[];
    float* Asm = smem;                    // NSTG stages of A
    float* Bsm = smem + NSTG * ASZ;       // NSTG stages of B

    const int tid  = threadIdx.x;
    const int lane = tid & 31;
    const int w    = tid >> 5;
    const int wm   = w & 1;
    const int wn   = w >> 1;
    const int g    = lane >> 2;
    const int tg   = lane & 3;

    const float* Ag = A  + (size_t)by * 128 * K;
    const float* Bg = Bm + (size_t)bx * 128;

    const int ar0 = tid >> 2,  ac0 = (tid & 3) * 4;   // A rows 0..63
    const int br0 = tid >> 5;                          // B k-rows 0..7
    const int br1 = br0 + 8;
    const int bc  = (tid & 31) * 4;

    const uint32_t aBase = (uint32_t)__cvta_generic_to_shared(Asm);
    const uint32_t bBase = (uint32_t)__cvta_generic_to_shared(Bsm);
    const uint32_t aOff0 = (ar0 * AS + ac0) * 4;
    const uint32_t aOff1 = ((ar0 + 64) * AS + ac0) * 4;
    const uint32_t bOff0 = (br0 * BS + bc) * 4;
    const uint32_t bOff1 = (br1 * BS + bc) * 4;

    auto issue_stage = [&](int st, int k0) {
        const int kb = k0 * 16;
        const uint32_t aS = aBase + st * ASZ * 4;
        const uint32_t bS = bBase + st * BSZ * 4;
        cp16(aS + aOff0, &Ag[(size_t)ar0 * K + kb + ac0]);
        cp16(aS + aOff1, &Ag[(size_t)(ar0 + 64) * K + kb + ac0]);
        cp16(bS + bOff0, &Bg[(size_t)(kb + br0) * N + bc]);
        cp16(bS + bOff1, &Bg[(size_t)(kb + br1) * N + bc]);
        cp_commit();
    };

    float acc[4][4][4];
    #pragma unroll
    for (int i = 0; i < 4; i++)
        #pragma unroll
        for (int j = 0; j < 4; j++)
            #pragma unroll
            for (int r = 0; r < 4; r++) acc[i][j][r] = 0.f;

    const int NIT = K / 16;

    issue_stage(0, 0);
    issue_stage(1, 1);
    issue_stage(2, 2);

    for (int k0 = 0; k0 < NIT; k0++) {
        cp_wait<2>();
        __syncthreads();

        const float* as = Asm + (k0 & 3) * ASZ;
        const float* bs = Bsm + (k0 & 3) * BSZ;
        #pragma unroll
        for (int kc = 0; kc < 2; kc++) {
            const int kb = kc * 8;
            uint32_t afrag[4][4], bfrag[4][2];
            #pragma unroll
            for (int mt = 0; mt < 4; mt++) {
                const int rb = wm * 64 + mt * 16;
                afrag[mt][0] = f2tf(as[(rb + g)     * AS + kb + tg]);
                afrag[mt][1] = f2tf(as[(rb + g + 8) * AS + kb + tg]);
                afrag[mt][2] = f2tf(as[(rb + g)     * AS + kb + tg + 4]);
                afrag[mt][3] = f2tf(as[(rb + g + 8) * AS + kb + tg + 4]);
            }
            #pragma unroll
            for (int nt = 0; nt < 4; nt++) {
                const int cb = wn * 32 + nt * 8 + g;
                bfrag[nt][0] = f2tf(bs[(kb + tg)     * BS + cb]);
                bfrag[nt][1] = f2tf(bs[(kb + tg + 4) * BS + cb]);
            }
            #pragma unroll
            for (int mt = 0; mt < 4; mt++)
                #pragma unroll
                for (int nt = 0; nt < 4; nt++)
                    mma_tf32(acc[mt][nt], afrag[mt], bfrag[nt]);
        }

        if (k0 + 3 < NIT)
            issue_stage((k0 + 3) & 3, k0 + 3);
    }

    // epilogue
    #pragma unroll
    for (int mt = 0; mt < 4; mt++) {
        const int gr = by * 128 + wm * 64 + mt * 16 + g;
        #pragma unroll
        for (int nt = 0; nt < 4; nt++) {
            const int gc = bx * 128 + wn * 32 + nt * 8 + 2 * tg;
            #pragma unroll
            for (int half = 0; half < 2; half++) {
                const size_t base = (size_t)(gr + half * 8) * N + gc;
                float v0 = acc[mt][nt][half * 2 + 0];
                float v1 = acc[mt][nt][half * 2 + 1];
                if (HAS_BIAS) { v0 += bias[gc]; v1 += bias[gc + 1]; }
                if (HAS_RES)  { v0 += res[base]; v1 += res[base + 1]; }
                if (RELU)     { v0 = fmaxf(v0, 0.f); v1 = fmaxf(v1, 0.f); }
                C[base]     = v0;
                C[base + 1] = v1;
            }
        }
    }
}

template<bool HAS_BIAS, bool HAS_RES, bool RELU>
__global__ __launch_bounds__(256, 2)
void tgemm(int N, int K,
           const float* __restrict__ A,
           const float* __restrict__ Bm,
           const float* __restrict__ bias,
           const float* __restrict__ res,
           float* __restrict__ C)
{
    gemm_body<HAS_BIAS, HAS_RES, RELU>(N, K, A, Bm, bias, res, C,
                                       blockIdx.x, blockIdx.y);
}

struct QKVArgs {
    const float* w[3];
    const float* b[3];
    float*       o[3];
};

__global__ __launch_bounds__(256, 2)
void tgemm_qkv(const float* __restrict__ A, QKVArgs args)
{
    const int z = blockIdx.z;
    gemm_body<true, false, false>(D, D, A, args.w[z], args.b[z], nullptr,
                                  args.o[z], blockIdx.x, blockIdx.y);
}

// ---------------------------------------------------------------------------
// Tensor-core flash attention — R15 + in-place tf32 conversion of the K/V
// stage (value-identical: same f2tf on same values, done once by the block
// instead of 8x redundantly per warp). One extra barrier per k-tile.
// Smem: QPs 128x68 + 2 x (K 64x68) + 2 x (V 64x68) = 104448 B.
// ---------------------------------------------------------------------------
constexpr int ATP = 68;
constexpr int AKV = 64 * ATP;
constexpr int ATTN_SMEM = (128 * ATP + 4 * AKV) * 4;

__global__ __launch_bounds__(256, 1)
void attn_kernel(const float* __restrict__ Q, const float* __restrict__ K,
                 const float* __restrict__ Vv, float* __restrict__ O)
{
    extern __shared__ float smx[];
    float* QPs = smx;                    // 128 x 68 (Q fragments, then P)
    float* Ks  = smx + 128 * ATP;        // 2 stages x 64 x 68
    float* Vs  = Ks  + 2 * AKV;          // 2 stages x 64 x 68

    const int qt = blockIdx.x;
    const int h = blockIdx.y, b = blockIdx.z;
    const int tid  = threadIdx.x;
    const int lane = tid & 31;
    const int w    = tid >> 5;
    const int g    = lane >> 2;
    const int tg   = lane & 3;

    const size_t base = (size_t)b * S * D + (size_t)h * HD;
    const float scale = 0.03125f;

    const uint32_t kBase = (uint32_t)__cvta_generic_to_shared(Ks);
    const uint32_t vBase = (uint32_t)__cvta_generic_to_shared(Vs);

    auto issue_kv = [&](int kt, int st) {
        #pragma unroll
        for (int p = 0; p < 4; p++) {
            const int v = tid + p * 256;
            const int r = v >> 4, c = (v & 15) * 4;
            const size_t grow = base + (size_t)(kt * 64 + r) * D + c;
            const uint32_t soff = (st * AKV + r * ATP + c) * 4;
            cp16(kBase + soff, &K[grow]);
            cp16(vBase + soff, &Vv[grow]);
        }
        cp_commit();
    };

    issue_kv(0, 0);

    // stage Q (scaled, tf32) — identical expressions to R15
    #pragma unroll
    for (int p = 0; p < 8; p++) {
        const int v = tid + p * 256;
        const int r = v >> 4, c = (v & 15) * 4;
        float4 q4 = *reinterpret_cast<const float4*>(
            &Q[base + (size_t)(qt * 128 + r) * D + c]);
        QPs[r * ATP + c + 0] = __uint_as_float(f2tf(q4.x * scale));
        QPs[r * ATP + c + 1] = __uint_as_float(f2tf(q4.y * scale));
        QPs[r * ATP + c + 2] = __uint_as_float(f2tf(q4.z * scale));
        QPs[r * ATP + c + 3] = __uint_as_float(f2tf(q4.w * scale));
    }
    __syncthreads();

    const int r0 = w * 16 + g;
    uint32_t qf[8][4];
    #pragma unroll
    for (int kd = 0; kd < 8; kd++) {
        qf[kd][0] = __float_as_uint(QPs[r0       * ATP + kd * 8 + tg]);
        qf[kd][1] = __float_as_uint(QPs[(r0 + 8) * ATP + kd * 8 + tg]);
        qf[kd][2] = __float_as_uint(QPs[r0       * ATP + kd * 8 + tg + 4]);
        qf[kd][3] = __float_as_uint(QPs[(r0 + 8) * ATP + kd * 8 + tg + 4]);
    }
    __syncthreads();    // QPs now free for P

    float m0 = -INFINITY, m1 = -INFINITY, l0 = 0.f, l1 = 0.f;
    float oa[8][4];
    #pragma unroll
    for (int dt = 0; dt < 8; dt++)
        #pragma unroll
        for (int c = 0; c < 4; c++) oa[dt][c] = 0.f;

    const int q0g = qt * 128 + w * 16 + g;
    const int q1g = q0g + 8;
    const int ktmax = 2 * qt + 1;

    for (int kt = 0; kt <= ktmax; kt++) {
        const int cur = kt & 1;
        if (kt < ktmax) { issue_kv(kt + 1, cur ^ 1); cp_wait<1>(); }
        else            { cp_wait<0>(); }
        __syncthreads();   // stage `cur` raw data visible to all threads

        float* ksm = Ks + cur * AKV;
        float* vsm = Vs + cur * AKV;

        // in-place tf32 conversion of stage `cur` (once per block, not 8x/warp)
        #pragma unroll
        for (int p = 0; p < 4; p++) {
            const int v = tid + p * 256;
            const int r = v >> 4, c = (v & 15) * 4;
            float4* kp = reinterpret_cast<float4*>(&ksm[r * ATP + c]);
            float4* vp = reinterpret_cast<float4*>(&vsm[r * ATP + c]);
            float4 kw = *kp, vw = *vp;
            *reinterpret_cast<uint4*>(kp) =
                make_uint4(f2tf(kw.x), f2tf(kw.y), f2tf(kw.z), f2tf(kw.w));
            *reinterpret_cast<uint4*>(vp) =
                make_uint4(f2tf(vw.x), f2tf(vw.y), f2tf(vw.z), f2tf(vw.w));
        }
        __syncthreads();   // converted stage visible

        const float* ks = ksm;
        const float* vs = vsm;

        // S = Q K^T (plain loads; tiles already tf32)
        float sa[8][4];
        #pragma unroll
        for (int nt = 0; nt < 8; nt++)
            #pragma unroll
            for (int c = 0; c < 4; c++) sa[nt][c] = 0.f;

        #pragma unroll
        for (int kd = 0; kd < 8; kd++) {
            #pragma unroll
            for (int nt = 0; nt < 8; nt++) {
                uint32_t bf[2];
                bf[0] = __float_as_uint(ks[(nt * 8 + g) * ATP + kd * 8 + tg]);
                bf[1] = __float_as_uint(ks[(nt * 8 + g) * ATP + kd * 8 + tg + 4]);
                mma_tf32(sa[nt], qf[kd], bf);
            }
        }

        // causal mask near diagonal
        if (kt >= 2 * qt) {
            #pragma unroll
            for (int nt = 0; nt < 8; nt++) {
                const int kc = kt * 64 + nt * 8 + 2 * tg;
                if (kc     > q0g) sa[nt][0] = -INFINITY;
                if (kc + 1 > q0g) sa[nt][1] = -INFINITY;
                if (kc     > q1g) sa[nt][2] = -INFINITY;
                if (kc + 1 > q1g) sa[nt][3] = -INFINITY;
            }
        }

        // online softmax — R15-exact expressions
        float tm0 = -INFINITY, tm1 = -INFINITY;
        #pragma unroll
        for (int nt = 0; nt < 8; nt++) {
            tm0 = fmaxf(tm0, fmaxf(sa[nt][0], sa[nt][1]));
            tm1 = fmaxf(tm1, fmaxf(sa[nt][2], sa[nt][3]));
        }
        #pragma unroll
        for (int off = 1; off < 4; off <<= 1) {
            tm0 = fmaxf(tm0, __shfl_xor_sync(0xffffffffu, tm0, off));
            tm1 = fmaxf(tm1, __shfl_xor_sync(0xffffffffu, tm1, off));
        }
        const float nm0 = fmaxf(m0, tm0);
        const float nm1 = fmaxf(m1, tm1);
        const float al0 = __expf(m0 - nm0);
        const float al1 = __expf(m1 - nm1);

        float rs0 = 0.f, rs1 = 0.f;
        #pragma unroll
        for (int nt = 0; nt < 8; nt++) {
            const float p00 = __expf(sa[nt][0] - nm0);
            const float p01 = __expf(sa[nt][1] - nm0);
            const float p10 = __expf(sa[nt][2] - nm1);
            const float p11 = __expf(sa[nt][3] - nm1);
            rs0 += p00 + p01;
            rs1 += p10 + p11;
            QPs[r0       * ATP + nt * 8 + 2 * tg]     = __uint_as_float(f2tf(p00));
            QPs[r0       * ATP + nt * 8 + 2 * tg + 1] = __uint_as_float(f2tf(p01));
            QPs[(r0 + 8) * ATP + nt * 8 + 2 * tg]     = __uint_as_float(f2tf(p10));
            QPs[(r0 + 8) * ATP + nt * 8 + 2 * tg + 1] = __uint_as_float(f2tf(p11));
        }
        #pragma unroll
        for (int off = 1; off < 4; off <<= 1) {
            rs0 += __shfl_xor_sync(0xffffffffu, rs0, off);
            rs1 += __shfl_xor_sync(0xffffffffu, rs1, off);
        }
        l0 = l0 * al0 + rs0;
        l1 = l1 * al1 + rs1;
        m0 = nm0;
        m1 = nm1;
        #pragma unroll
        for (int dt = 0; dt < 8; dt++) {
            oa[dt][0] *= al0; oa[dt][1] *= al0;
            oa[dt][2] *= al1; oa[dt][3] *= al1;
        }
        __syncwarp();   // P region is warp-private (as in R15)

        // O += P V (plain loads; V already tf32)
        #pragma unroll
        for (int kk = 0; kk < 8; kk++) {
            uint32_t af[4];
            af[0] = __float_as_uint(QPs[r0       * ATP + kk * 8 + tg]);
            af[1] = __float_as_uint(QPs[(r0 + 8) * ATP + kk * 8 + tg]);
            af[2] = __float_as_uint(QPs[r0       * ATP + kk * 8 + tg + 4]);
            af[3] = __float_as_uint(QPs[(r0 + 8) * ATP + kk * 8 + tg + 4]);
            #pragma unroll
            for (int dt = 0; dt < 8; dt++) {
                uint32_t bf[2];
                bf[0] = __float_as_uint(vs[(kk * 8 + tg)     * ATP + dt * 8 + g]);
                bf[1] = __float_as_uint(vs[(kk * 8 + tg + 4) * ATP + dt * 8 + g]);
                mma_tf32(oa[dt], af, bf);
            }
        }
        __syncthreads();   // all reads of stage `cur` done before next overwrite
    }

    const float inv0 = 1.0f / l0;
    const float inv1 = 1.0f / l1;
    #pragma unroll
    for (int dt = 0; dt < 8; dt++) {
        const int col = dt * 8 + 2 * tg;
        float2 v0 = make_float2(oa[dt][0] * inv0, oa[dt][1] * inv0);
        float2 v1 = make_float2(oa[dt][2] * inv1, oa[dt][3] * inv1);
        *reinterpret_cast<float2*>(&O[base + (size_t)q0g * D + col]) = v0;
        *reinterpret_cast<float2*>(&O[base + (size_t)q1g * D + col]) = v1;
    }
}

// ---------------------------------------------------------------------------
// Launch (R15-exact)
// ---------------------------------------------------------------------------
extern "C" void kernel_launch(void* const* d_in, const int* in_sizes, int n_in,
                              void* d_out, int out_size)
{
    (void)in_sizes; (void)n_in; (void)out_size;
    const int*   x    = (const int*)  d_in[0];
    const float* emb  = (const float*)d_in[1];
    const float* pe   = (const float*)d_in[2];
    const float* ln1g = (const float*)d_in[3];
    const float* ln1b = (const float*)d_in[4];
    const float* wq   = (const float*)d_in[5];
    const float* bq   = (const float*)d_in[6];
    const float* wk   = (const float*)d_in[7];
    const float* bk   = (const float*)d_in[8];
    const float* wv   = (const float*)d_in[9];
    const float* bv   = (const float*)d_in[10];
    const float* wo   = (const float*)d_in[11];
    const float* bo   = (const float*)d_in[12];
    const float* ln2g = (const float*)d_in[13];
    const float* ln2b = (const float*)d_in[14];
    const float* w1   = (const float*)d_in[15];
    const float* b1   = (const float*)d_in[16];
    const float* w2   = (const float*)d_in[17];
    const float* b2   = (const float*)d_in[18];
    const float* lnfg = (const float*)d_in[19];
    const float* lnfb = (const float*)d_in[20];
    const float* wout = (const float*)d_in[21];
    float* out = (float*)d_out;

    float *h, *a, *q, *k, *v, *t, *f;
    cudaGetSymbolAddress((void**)&h, g_h);
    cudaGetSymbolAddress((void**)&a, g_a);
    cudaGetSymbolAddress((void**)&q, g_q);
    cudaGetSymbolAddress((void**)&k, g_k);
    cudaGetSymbolAddress((void**)&v, g_v);
    cudaGetSymbolAddress((void**)&t, g_t);
    cudaGetSymbolAddress((void**)&f, g_f);

    cudaFuncSetAttribute(attn_kernel,
                         cudaFuncAttributeMaxDynamicSharedMemorySize, ATTN_SMEM);
    cudaFuncSetAttribute(tgemm<true,  true,  false>,
                         cudaFuncAttributeMaxDynamicSharedMemorySize, GEMM_SMEM);
    cudaFuncSetAttribute(tgemm<true,  false, true>,
                         cudaFuncAttributeMaxDynamicSharedMemorySize, GEMM_SMEM);
    cudaFuncSetAttribute(tgemm<false, false, false>,
                         cudaFuncAttributeMaxDynamicSharedMemorySize, GEMM_SMEM);
    cudaFuncSetAttribute(tgemm_qkv,
                         cudaFuncAttributeMaxDynamicSharedMemorySize, GEMM_SMEM);

    const dim3 gD  (D  / 128, M / 128);
    const dim3 gDH (DH / 128, M / 128);
    const dim3 gV  (V  / 128, M / 128);
    const dim3 gQKV(D  / 128, M / 128, 3);
    const dim3 gAttn(S / 128, NH, B);

    embed_kernel<<<M, 256>>>(x, emb, pe, h);

    for (int l = 0; l < NL; l++) {
        const size_t wOff = (size_t)l * D * D;
        ln_kernel<<<M, 256>>>(h, ln1g + l * D, ln1b + l * D, a);
        QKVArgs qa;
        qa.w[0] = wq + wOff; qa.b[0] = bq + l * D; qa.o[0] = q;
        qa.w[1] = wk + wOff; qa.b[1] = bk + l * D; qa.o[1] = k;
        qa.w[2] = wv + wOff; qa.b[2] = bv + l * D; qa.o[2] = v;
        tgemm_qkv<<<gQKV, 256, GEMM_SMEM>>>(a, qa);
        attn_kernel<<<gAttn, 256, ATTN_SMEM>>>(q, k, v, t);
        tgemm<true, true,  false><<<gD, 256, GEMM_SMEM>>>(D, D, t, wo + wOff, bo + l * D, h, h);
        ln_kernel<<<M, 256>>>(h, ln2g + l * D, ln2b + l * D, a);
        tgemm<true, false, true ><<<gDH, 256, GEMM_SMEM>>>(DH, D, a, w1 + (size_t)l * D * DH, b1 + l * DH, nullptr, f);
        tgemm<true, true,  false><<<gD, 256, GEMM_SMEM>>>(D, DH, f, w2 + (size_t)l * DH * D, b2 + l * D, h, h);
    }

    ln_kernel<<<M, 256>>>(h, lnfg, lnfb, a);
    tgemm<false, false, false><<<gV, 256, GEMM_SMEM>>>(
        V, D, a, wout, nullptr, nullptr, out);
}

// round 17
// speedup vs baseline: 1.0199x; 1.0199x over previous
#include <cuda_runtime.h>
#include <cuda_bf16.h>
#include <math.h>
#include <stdint.h>

// Problem constants
constexpr int B  = 2;
constexpr int S  = 1024;
constexpr int V  = 32000;
constexpr int D  = 1024;
constexpr int DH = 4096;
constexpr int NL = 4;
constexpr int NH = 16;
constexpr int HD = 64;
constexpr int M  = B * S;

// ---------------------------------------------------------------------------
// Scratch (device globals)
// ---------------------------------------------------------------------------
__device__ float g_h[M * D];
__device__ float g_a[M * D];
__device__ float g_q[M * D];
__device__ float g_k[M * D];
__device__ float g_v[M * D];
__device__ float g_t[M * D];
__device__ float g_f[M * DH];

// ---------------------------------------------------------------------------
// Embedding + positional encoding (R15-exact)
// ---------------------------------------------------------------------------
__global__ void embed_kernel(const int* __restrict__ x,
                             const float* __restrict__ emb,
                             const float* __restrict__ pe,
                             float* __restrict__ out)
{
    const int i   = blockIdx.x;
    const int s   = i % S;
    const int tok = x[i];
    const float4* e = reinterpret_cast<const float4*>(emb + (size_t)tok * D);
    const float4* p = reinterpret_cast<const float4*>(pe  + (size_t)s   * D);
    float4*       o = reinterpret_cast<float4*>(out + (size_t)i * D);
    const int t = threadIdx.x;
    float4 a = e[t], b = p[t];
    o[t] = make_float4(a.x + b.x, a.y + b.y, a.z + b.z, a.w + b.w);
}

// ---------------------------------------------------------------------------
// LayerNorm (R15-exact)
// ---------------------------------------------------------------------------
__global__ void ln_kernel(const float* __restrict__ X,
                          const float* __restrict__ gam,
                          const float* __restrict__ bet,
                          float* __restrict__ Y)
{
    const int row = blockIdx.x;
    const float* x = X + (size_t)row * D;
    float*       y = Y + (size_t)row * D;
    __shared__ float sred[8];
    const int tid = threadIdx.x;

    float s = 0.f;
    for (int d = tid; d < D; d += 256) s += x[d];
    #pragma unroll
    for (int o = 16; o > 0; o >>= 1) s += __shfl_xor_sync(0xffffffffu, s, o);
    if ((tid & 31) == 0) sred[tid >> 5] = s;
    __syncthreads();
    float mean = 0.f;
    #pragma unroll
    for (int w = 0; w < 8; w++) mean += sred[w];
    mean *= (1.0f / D);
    __syncthreads();

    float vs = 0.f;
    for (int d = tid; d < D; d += 256) { float t = x[d] - mean; vs += t * t; }
    #pragma unroll
    for (int o = 16; o > 0; o >>= 1) vs += __shfl_xor_sync(0xffffffffu, vs, o);
    if ((tid & 31) == 0) sred[tid >> 5] = vs;
    __syncthreads();
    float var = 0.f;
    #pragma unroll
    for (int w = 0; w < 8; w++) var += sred[w];
    var *= (1.0f / D);
    const float rstd = rsqrtf(var + 1e-5f);

    for (int d = tid; d < D; d += 256)
        y[d] = (x[d] - mean) * rstd * gam[d] + bet[d];
}

// ---------------------------------------------------------------------------
// tf32 helpers
// ---------------------------------------------------------------------------
__device__ __forceinline__ uint32_t f2tf(float x) {
    uint32_t r;
    asm("cvt.rna.tf32.f32 %0, %1;" : "=r"(r) : "f"(x));
    return r;
}

__device__ __forceinline__ void mma_tf32(float* d,
                                         const uint32_t* a,
                                         const uint32_t* b)
{
    asm volatile(
        "mma.sync.aligned.m16n8k8.row.col.f32.tf32.tf32.f32 "
        "{%0,%1,%2,%3}, {%4,%5,%6,%7}, {%8,%9}, {%0,%1,%2,%3};\n"
        : "+f"(d[0]), "+f"(d[1]), "+f"(d[2]), "+f"(d[3])
        : "r"(a[0]), "r"(a[1]), "r"(a[2]), "r"(a[3]),
          "r"(b[0]), "r"(b[1]));
}

__device__ __forceinline__ void cp16(uint32_t dst_smem, const void* src) {
    asm volatile("cp.async.ca.shared.global [%0], [%1], 16;"
                 :: "r"(dst_smem), "l"(src));
}
__device__ __forceinline__ void cp_commit() {
    asm volatile("cp.async.commit_group;");
}
template<int N>
__device__ __forceinline__ void cp_wait() {
    asm volatile("cp.async.wait_group %0;" :: "n"(N));
}

// ---------------------------------------------------------------------------
// TF32 tensor-core GEMM, cp.async 4-stage pipeline (R15-exact, BM=128 only)
// ---------------------------------------------------------------------------
constexpr int AS = 20;                    // A row stride (words), [row][k]
constexpr int BS = 136;                   // B row stride (words), [k][col]
constexpr int ASZ = 128 * AS;             // 2560 words / stage
constexpr int BSZ = 16 * BS;              // 2176 words / stage
constexpr int NSTG = 4;
constexpr int GEMM_SMEM = NSTG * (ASZ + BSZ) * 4;   // 75776 B

template<bool HAS_BIAS, bool HAS_RES, bool RELU>
__device__ __forceinline__
void gemm_body(int N, int K,
               const float* __restrict__ A,
               const float* __restrict__ Bm,
               const float* __restrict__ bias,
               const float* __restrict__ res,
               float* __restrict__ C,
               int bx, int by)
{
    extern __shared__ float smem[];
    float* Asm = smem;                    // NSTG stages of A
    float* Bsm = smem + NSTG * ASZ;       // NSTG stages of B

    const int tid  = threadIdx.x;
    const int lane = tid & 31;
    const int w    = tid >> 5;
    const int wm   = w & 1;
    const int wn   = w >> 1;
    const int g    = lane >> 2;
    const int tg   = lane & 3;

    const float* Ag = A  + (size_t)by * 128 * K;
    const float* Bg = Bm + (size_t)bx * 128;

    const int ar0 = tid >> 2,  ac0 = (tid & 3) * 4;   // A rows 0..63
    const int br0 = tid >> 5;                          // B k-rows 0..7
    const int br1 = br0 + 8;
    const int bc  = (tid & 31) * 4;

    const uint32_t aBase = (uint32_t)__cvta_generic_to_shared(Asm);
    const uint32_t bBase = (uint32_t)__cvta_generic_to_shared(Bsm);
    const uint32_t aOff0 = (ar0 * AS + ac0) * 4;
    const uint32_t aOff1 = ((ar0 + 64) * AS + ac0) * 4;
    const uint32_t bOff0 = (br0 * BS + bc) * 4;
    const uint32_t bOff1 = (br1 * BS + bc) * 4;

    auto issue_stage = [&](int st, int k0) {
        const int kb = k0 * 16;
        const uint32_t aS = aBase + st * ASZ * 4;
        const uint32_t bS = bBase + st * BSZ * 4;
        cp16(aS + aOff0, &Ag[(size_t)ar0 * K + kb + ac0]);
        cp16(aS + aOff1, &Ag[(size_t)(ar0 + 64) * K + kb + ac0]);
        cp16(bS + bOff0, &Bg[(size_t)(kb + br0) * N + bc]);
        cp16(bS + bOff1, &Bg[(size_t)(kb + br1) * N + bc]);
        cp_commit();
    };

    float acc[4][4][4];
    #pragma unroll
    for (int i = 0; i < 4; i++)
        #pragma unroll
        for (int j = 0; j < 4; j++)
            #pragma unroll
            for (int r = 0; r < 4; r++) acc[i][j][r] = 0.f;

    const int NIT = K / 16;

    issue_stage(0, 0);
    issue_stage(1, 1);
    issue_stage(2, 2);

    for (int k0 = 0; k0 < NIT; k0++) {
        cp_wait<2>();
        __syncthreads();

        const float* as = Asm + (k0 & 3) * ASZ;
        const float* bs = Bsm + (k0 & 3) * BSZ;
        #pragma unroll
        for (int kc = 0; kc < 2; kc++) {
            const int kb = kc * 8;
            uint32_t afrag[4][4], bfrag[4][2];
            #pragma unroll
            for (int mt = 0; mt < 4; mt++) {
                const int rb = wm * 64 + mt * 16;
                afrag[mt][0] = f2tf(as[(rb + g)     * AS + kb + tg]);
                afrag[mt][1] = f2tf(as[(rb + g + 8) * AS + kb + tg]);
                afrag[mt][2] = f2tf(as[(rb + g)     * AS + kb + tg + 4]);
                afrag[mt][3] = f2tf(as[(rb + g + 8) * AS + kb + tg + 4]);
            }
            #pragma unroll
            for (int nt = 0; nt < 4; nt++) {
                const int cb = wn * 32 + nt * 8 + g;
                bfrag[nt][0] = f2tf(bs[(kb + tg)     * BS + cb]);
                bfrag[nt][1] = f2tf(bs[(kb + tg + 4) * BS + cb]);
            }
            #pragma unroll
            for (int mt = 0; mt < 4; mt++)
                #pragma unroll
                for (int nt = 0; nt < 4; nt++)
                    mma_tf32(acc[mt][nt], afrag[mt], bfrag[nt]);
        }

        if (k0 + 3 < NIT)
            issue_stage((k0 + 3) & 3, k0 + 3);
    }

    // epilogue
    #pragma unroll
    for (int mt = 0; mt < 4; mt++) {
        const int gr = by * 128 + wm * 64 + mt * 16 + g;
        #pragma unroll
        for (int nt = 0; nt < 4; nt++) {
            const int gc = bx * 128 + wn * 32 + nt * 8 + 2 * tg;
            #pragma unroll
            for (int half = 0; half < 2; half++) {
                const size_t base = (size_t)(gr + half * 8) * N + gc;
                float v0 = acc[mt][nt][half * 2 + 0];
                float v1 = acc[mt][nt][half * 2 + 1];
                if (HAS_BIAS) { v0 += bias[gc]; v1 += bias[gc + 1]; }
                if (HAS_RES)  { v0 += res[base]; v1 += res[base + 1]; }
                if (RELU)     { v0 = fmaxf(v0, 0.f); v1 = fmaxf(v1, 0.f); }
                C[base]     = v0;
                C[base + 1] = v1;
            }
        }
    }
}

template<bool HAS_BIAS, bool HAS_RES, bool RELU>
__global__ __launch_bounds__(256, 2)
void tgemm(int N, int K,
           const float* __restrict__ A,
           const float* __restrict__ Bm,
           const float* __restrict__ bias,
           const float* __restrict__ res,
           float* __restrict__ C)
{
    gemm_body<HAS_BIAS, HAS_RES, RELU>(N, K, A, Bm, bias, res, C,
                                       blockIdx.x, blockIdx.y);
}

struct QKVArgs {
    const float* w[3];
    const float* b[3];
    float*       o[3];
};

__global__ __launch_bounds__(256, 2)
void tgemm_qkv(const float* __restrict__ A, QKVArgs args)
{
    const int z = blockIdx.z;
    gemm_body<true, false, false>(D, D, A, args.w[z], args.b[z], nullptr,
                                  args.o[z], blockIdx.x, blockIdx.y);
}

// ---------------------------------------------------------------------------
// Tensor-core flash attention — R15 inner math, restructured to 64 q-rows
// per CTA with 128 threads (4 warps x 16 rows) so 2 CTAs fit per SM
// (regs 148*128*2 << 64K; smem 87040*2 = 174KB <= 228KB).
// K/V staged RAW via cp.async double buffer, consumer-side f2tf (as R15).
// Grid: (S/64, NH, B) = 512 blocks.
// ---------------------------------------------------------------------------
constexpr int ATP = 68;
constexpr int AKV = 64 * ATP;
constexpr int ATTN_SMEM = (64 * ATP + 4 * AKV) * 4;   // 87040 B

__global__ __launch_bounds__(128, 2)
void attn_kernel(const float* __restrict__ Q, const float* __restrict__ K,
                 const float* __restrict__ Vv, float* __restrict__ O)
{
    extern __shared__ float smx[];
    float* QPs = smx;                    // 64 x 68 (Q fragments, then P)
    float* Ks  = smx + 64 * ATP;         // 2 stages x 64 x 68 (raw fp32)
    float* Vs  = Ks  + 2 * AKV;          // 2 stages x 64 x 68 (raw fp32)

    const int qt = blockIdx.x;           // 64-row q tile
    const int h = blockIdx.y, b = blockIdx.z;
    const int tid  = threadIdx.x;
    const int lane = tid & 31;
    const int w    = tid >> 5;           // 0..3
    const int g    = lane >> 2;
    const int tg   = lane & 3;

    const size_t base = (size_t)b * S * D + (size_t)h * HD;
    const float scale = 0.03125f;

    const uint32_t kBase = (uint32_t)__cvta_generic_to_shared(Ks);
    const uint32_t vBase = (uint32_t)__cvta_generic_to_shared(Vs);

    auto issue_kv = [&](int kt, int st) {
        #pragma unroll
        for (int p = 0; p < 8; p++) {
            const int v = tid + p * 128;
            const int r = v >> 4, c = (v & 15) * 4;
            const size_t grow = base + (size_t)(kt * 64 + r) * D + c;
            const uint32_t soff = (st * AKV + r * ATP + c) * 4;
            cp16(kBase + soff, &K[grow]);
            cp16(vBase + soff, &Vv[grow]);
        }
        cp_commit();
    };

    issue_kv(0, 0);

    // stage Q (scaled, tf32) — identical expressions to R15
    #pragma unroll
    for (int p = 0; p < 8; p++) {
        const int v = tid + p * 128;
        const int r = v >> 4, c = (v & 15) * 4;
        float4 q4 = *reinterpret_cast<const float4*>(
            &Q[base + (size_t)(qt * 64 + r) * D + c]);
        QPs[r * ATP + c + 0] = __uint_as_float(f2tf(q4.x * scale));
        QPs[r * ATP + c + 1] = __uint_as_float(f2tf(q4.y * scale));
        QPs[r * ATP + c + 2] = __uint_as_float(f2tf(q4.z * scale));
        QPs[r * ATP + c + 3] = __uint_as_float(f2tf(q4.w * scale));
    }
    __syncthreads();

    const int r0 = w * 16 + g;           // 0..55
    uint32_t qf[8][4];
    #pragma unroll
    for (int kd = 0; kd < 8; kd++) {
        qf[kd][0] = __float_as_uint(QPs[r0       * ATP + kd * 8 + tg]);
        qf[kd][1] = __float_as_uint(QPs[(r0 + 8) * ATP + kd * 8 + tg]);
        qf[kd][2] = __float_as_uint(QPs[r0       * ATP + kd * 8 + tg + 4]);
        qf[kd][3] = __float_as_uint(QPs[(r0 + 8) * ATP + kd * 8 + tg + 4]);
    }
    __syncthreads();    // QPs now free for P

    float m0 = -INFINITY, m1 = -INFINITY, l0 = 0.f, l1 = 0.f;
    float oa[8][4];
    #pragma unroll
    for (int dt = 0; dt < 8; dt++)
        #pragma unroll
        for (int c = 0; c < 4; c++) oa[dt][c] = 0.f;

    const int q0g = qt * 64 + w * 16 + g;
    const int q1g = q0g + 8;
    const int ktmax = qt;                // causal range for 64-row tiles

    for (int kt = 0; kt <= ktmax; kt++) {
        const int cur = kt & 1;
        if (kt < ktmax) { issue_kv(kt + 1, cur ^ 1); cp_wait<1>(); }
        else            { cp_wait<0>(); }
        __syncthreads();   // stage `cur` visible to all threads

        const float* ks = Ks + cur * AKV;
        const float* vs = Vs + cur * AKV;

        // S = Q K^T (consumer-side f2tf on raw K)
        float sa[8][4];
        #pragma unroll
        for (int nt = 0; nt < 8; nt++)
            #pragma unroll
            for (int c = 0; c < 4; c++) sa[nt][c] = 0.f;

        #pragma unroll
        for (int kd = 0; kd < 8; kd++) {
            #pragma unroll
            for (int nt = 0; nt < 8; nt++) {
                uint32_t bf[2];
                bf[0] = f2tf(ks[(nt * 8 + g) * ATP + kd * 8 + tg]);
                bf[1] = f2tf(ks[(nt * 8 + g) * ATP + kd * 8 + tg + 4]);
                mma_tf32(sa[nt], qf[kd], bf);
            }
        }

        // causal mask (diagonal tile only)
        if (kt >= qt) {
            #pragma unroll
            for (int nt = 0; nt < 8; nt++) {
                const int kc = kt * 64 + nt * 8 + 2 * tg;
                if (kc     > q0g) sa[nt][0] = -INFINITY;
                if (kc + 1 > q0g) sa[nt][1] = -INFINITY;
                if (kc     > q1g) sa[nt][2] = -INFINITY;
                if (kc + 1 > q1g) sa[nt][3] = -INFINITY;
            }
        }

        // online softmax — R15-exact expressions
        float tm0 = -INFINITY, tm1 = -INFINITY;
        #pragma unroll
        for (int nt = 0; nt < 8; nt++) {
            tm0 = fmaxf(tm0, fmaxf(sa[nt][0], sa[nt][1]));
            tm1 = fmaxf(tm1, fmaxf(sa[nt][2], sa[nt][3]));
        }
        #pragma unroll
        for (int off = 1; off < 4; off <<= 1) {
            tm0 = fmaxf(tm0, __shfl_xor_sync(0xffffffffu, tm0, off));
            tm1 = fmaxf(tm1, __shfl_xor_sync(0xffffffffu, tm1, off));
        }
        const float nm0 = fmaxf(m0, tm0);
        const float nm1 = fmaxf(m1, tm1);
        const float al0 = __expf(m0 - nm0);
        const float al1 = __expf(m1 - nm1);

        float rs0 = 0.f, rs1 = 0.f;
        #pragma unroll
        for (int nt = 0; nt < 8; nt++) {
            const float p00 = __expf(sa[nt][0] - nm0);
            const float p01 = __expf(sa[nt][1] - nm0);
            const float p10 = __expf(sa[nt][2] - nm1);
            const float p11 = __expf(sa[nt][3] - nm1);
            rs0 += p00 + p01;
            rs1 += p10 + p11;
            QPs[r0       * ATP + nt * 8 + 2 * tg]     = __uint_as_float(f2tf(p00));
            QPs[r0       * ATP + nt * 8 + 2 * tg + 1] = __uint_as_float(f2tf(p01));
            QPs[(r0 + 8) * ATP + nt * 8 + 2 * tg]     = __uint_as_float(f2tf(p10));
            QPs[(r0 + 8) * ATP + nt * 8 + 2 * tg + 1] = __uint_as_float(f2tf(p11));
        }
        #pragma unroll
        for (int off = 1; off < 4; off <<= 1) {
            rs0 += __shfl_xor_sync(0xffffffffu, rs0, off);
            rs1 += __shfl_xor_sync(0xffffffffu, rs1, off);
        }
        l0 = l0 * al0 + rs0;
        l1 = l1 * al1 + rs1;
        m0 = nm0;
        m1 = nm1;
        #pragma unroll
        for (int dt = 0; dt < 8; dt++) {
            oa[dt][0] *= al0; oa[dt][1] *= al0;
            oa[dt][2] *= al1; oa[dt][3] *= al1;
        }
        __syncwarp();   // P region is warp-private (as in R15)

        // O += P V (consumer-side f2tf on raw V)
        #pragma unroll
        for (int kk = 0; kk < 8; kk++) {
            uint32_t af[4];
            af[0] = __float_as_uint(QPs[r0       * ATP + kk * 8 + tg]);
            af[1] = __float_as_uint(QPs[(r0 + 8) * ATP + kk * 8 + tg]);
            af[2] = __float_as_uint(QPs[r0       * ATP + kk * 8 + tg + 4]);
            af[3] = __float_as_uint(QPs[(r0 + 8) * ATP + kk * 8 + tg + 4]);
            #pragma unroll
            for (int dt = 0; dt < 8; dt++) {
                uint32_t bf[2];
                bf[0] = f2tf(vs[(kk * 8 + tg)     * ATP + dt * 8 + g]);
                bf[1] = f2tf(vs[(kk * 8 + tg + 4) * ATP + dt * 8 + g]);
                mma_tf32(oa[dt], af, bf);
            }
        }
        __syncthreads();   // all reads of stage `cur` done before next overwrite
    }

    const float inv0 = 1.0f / l0;
    const float inv1 = 1.0f / l1;
    #pragma unroll
    for (int dt = 0; dt < 8; dt++) {
        const int col = dt * 8 + 2 * tg;
        float2 v0 = make_float2(oa[dt][0] * inv0, oa[dt][1] * inv0);
        float2 v1 = make_float2(oa[dt][2] * inv1, oa[dt][3] * inv1);
        *reinterpret_cast<float2*>(&O[base + (size_t)q0g * D + col]) = v0;
        *reinterpret_cast<float2*>(&O[base + (size_t)q1g * D + col]) = v1;
    }
}

// ---------------------------------------------------------------------------
// Launch
// ---------------------------------------------------------------------------
extern "C" void kernel_launch(void* const* d_in, const int* in_sizes, int n_in,
                              void* d_out, int out_size)
{
    (void)in_sizes; (void)n_in; (void)out_size;
    const int*   x    = (const int*)  d_in[0];
    const float* emb  = (const float*)d_in[1];
    const float* pe   = (const float*)d_in[2];
    const float* ln1g = (const float*)d_in[3];
    const float* ln1b = (const float*)d_in[4];
    const float* wq   = (const float*)d_in[5];
    const float* bq   = (const float*)d_in[6];
    const float* wk   = (const float*)d_in[7];
    const float* bk   = (const float*)d_in[8];
    const float* wv   = (const float*)d_in[9];
    const float* bv   = (const float*)d_in[10];
    const float* wo   = (const float*)d_in[11];
    const float* bo   = (const float*)d_in[12];
    const float* ln2g = (const float*)d_in[13];
    const float* ln2b = (const float*)d_in[14];
    const float* w1   = (const float*)d_in[15];
    const float* b1   = (const float*)d_in[16];
    const float* w2   = (const float*)d_in[17];
    const float* b2   = (const float*)d_in[18];
    const float* lnfg = (const float*)d_in[19];
    const float* lnfb = (const float*)d_in[20];
    const float* wout = (const float*)d_in[21];
    float* out = (float*)d_out;

    float *h, *a, *q, *k, *v, *t, *f;
    cudaGetSymbolAddress((void**)&h, g_h);
    cudaGetSymbolAddress((void**)&a, g_a);
    cudaGetSymbolAddress((void**)&q, g_q);
    cudaGetSymbolAddress((void**)&k, g_k);
    cudaGetSymbolAddress((void**)&v, g_v);
    cudaGetSymbolAddress((void**)&t, g_t);
    cudaGetSymbolAddress((void**)&f, g_f);

    cudaFuncSetAttribute(attn_kernel,
                         cudaFuncAttributeMaxDynamicSharedMemorySize, ATTN_SMEM);
    cudaFuncSetAttribute(tgemm<true,  true,  false>,
                         cudaFuncAttributeMaxDynamicSharedMemorySize, GEMM_SMEM);
    cudaFuncSetAttribute(tgemm<true,  false, true>,
                         cudaFuncAttributeMaxDynamicSharedMemorySize, GEMM_SMEM);
    cudaFuncSetAttribute(tgemm<false, false, false>,
                         cudaFuncAttributeMaxDynamicSharedMemorySize, GEMM_SMEM);
    cudaFuncSetAttribute(tgemm_qkv,
                         cudaFuncAttributeMaxDynamicSharedMemorySize, GEMM_SMEM);

    const dim3 gD  (D  / 128, M / 128);
    const dim3 gDH (DH / 128, M / 128);
    const dim3 gV  (V  / 128, M / 128);
    const dim3 gQKV(D  / 128, M / 128, 3);
    const dim3 gAttn(S / 64, NH, B);

    embed_kernel<<<M, 256>>>(x, emb, pe, h);

    for (int l = 0; l < NL; l++) {
        const size_t wOff = (size_t)l * D * D;
        ln_kernel<<<M, 256>>>(h, ln1g + l * D, ln1b + l * D, a);
        QKVArgs qa;
        qa.w[0] = wq + wOff; qa.b[0] = bq + l * D; qa.o[0] = q;
        qa.w[1] = wk + wOff; qa.b[1] = bk + l * D; qa.o[1] = k;
        qa.w[2] = wv + wOff; qa.b[2] = bv + l * D; qa.o[2] = v;
        tgemm_qkv<<<gQKV, 256, GEMM_SMEM>>>(a, qa);
        attn_kernel<<<gAttn, 128, ATTN_SMEM>>>(q, k, v, t);
        tgemm<true, true,  false><<<gD, 256, GEMM_SMEM>>>(D, D, t, wo + wOff, bo + l * D, h, h);
        ln_kernel<<<M, 256>>>(h, ln2g + l * D, ln2b + l * D, a);
        tgemm<true, false, true ><<<gDH, 256, GEMM_SMEM>>>(DH, D, a, w1 + (size_t)l * D * DH, b1 + l * DH, nullptr, f);
        tgemm<true, true,  false><<<gD, 256, GEMM_SMEM>>>(D, DH, f, w2 + (size_t)l * DH * D, b2 + l * D, h, h);
    }

    ln_kernel<<<M, 256>>>(h, lnfg, lnfb, a);
    tgemm<false, false, false><<<gV, 256, GEMM_SMEM>>>(
        V, D, a, wout, nullptr, nullptr, out);
}